// round 14
// baseline (speedup 1.0000x reference)
#include <cuda_runtime.h>

// AccuracyMetricLoss: per-day (96-elem) RMS relative-error score, mean over days.
// score_d = (1 - sqrt(mean_j ((t-p)/max(t,thresh))^2)) * 100 ; out = mean_d score_d
//
// FINAL (converged, reproduced 3x at 31.232us; ncu kernel 30.1-31.9us across
// NAT clock jitter, ~5.0-5.2TB/s). Experiment matrix R4-R12: occupancy
// 37/50/62/93%, scalar vs float4 vs register-pipelined LDG, ldcs vs default
// policy, and a cp.async.bulk (TMA) smem pipeline — ALL land in the same
// 4.7-5.2TB/s band. The ceiling is a path-independent platform memory-system
// property (B300_MICROARCH: LTS cap is the same for LDG and TMA); this kernel
// sits at it with launch overhead fused away via last-block-finalize.
//
//  - 8-lanes-per-day float4 layout: 6 batched, fully-coalesced LDG.128/trip.
//  - __ldcs evict-first streaming loads (dataset 153.6MB >> 126MB L2;
//    default policy costs ~10% in the same clock regime).
//  - __launch_bounds__(256,4), 592 blocks, contiguous per-warp day ranges
//    (<=1 day skew).
//  - 3-shuffle in-group day reduction; score counted 8x/day, divided at end.
//  - last-block-finalizes: fixed-order double reduction (deterministic),
//    counter self-resets => graph-replayable.

#define T_LEN 96
#define F4_PER_DAY 24
#define NBLOCKS 592          // 4 * 148 SMs
#define NTHREADS 256         // 8 warps/block
#define WARPS_PER_BLOCK (NTHREADS / 32)
#define TOTAL_WARPS (NBLOCKS * WARPS_PER_BLOCK)

__device__ float g_partials[NBLOCKS];
__device__ unsigned int g_counter = 0;

__device__ __forceinline__ float day_err_sq(float4 t, float4 p, float thresh)
{
    float d0 = (t.x > thresh) ? t.x : thresh;
    float d1 = (t.y > thresh) ? t.y : thresh;
    float d2 = (t.z > thresh) ? t.z : thresh;
    float d3 = (t.w > thresh) ? t.w : thresh;
    float e0 = __fdividef(t.x - p.x, d0);
    float e1 = __fdividef(t.y - p.y, d1);
    float e2 = __fdividef(t.z - p.z, d2);
    float e3 = __fdividef(t.w - p.w, d3);
    return e0 * e0 + e1 * e1 + e2 * e2 + e3 * e3;
}

__global__ __launch_bounds__(NTHREADS, 4) void score_kernel(
    const float* __restrict__ pred,
    const float* __restrict__ tru,
    float* __restrict__ out,
    int num_days)
{
    const float cap    = 1602.1333333333334f;
    const float thresh = 0.2f * cap;
    const float inv_T  = 1.0f / 96.0f;

    const int lane = threadIdx.x & 31;
    const int g    = lane >> 3;          // day group within warp (0..3)
    const int k    = lane & 7;           // lane within group
    const int warp = (blockIdx.x * WARPS_PER_BLOCK) + (threadIdx.x >> 5);

    const float4* __restrict__ tru4  = (const float4*)tru;
    const float4* __restrict__ pred4 = (const float4*)pred;

    // contiguous per-warp day range: near-perfect balance (<=1 day skew)
    int day_s = (int)(((long)warp       * num_days) / TOTAL_WARPS);
    int day_e = (int)(((long)(warp + 1) * num_days) / TOTAL_WARPS);

    float acc = 0.0f;

    int day = day_s;
    for (; day + 4 <= day_e; day += 4) {
        // 6 fully-coalesced LDG.128 per warp, batched
        const long b = (long)(day + g) * F4_PER_DAY + k;
        float4 t0 = __ldcs(tru4  + b);
        float4 t1 = __ldcs(tru4  + b + 8);
        float4 t2 = __ldcs(tru4  + b + 16);
        float4 p0 = __ldcs(pred4 + b);
        float4 p1 = __ldcs(pred4 + b + 8);
        float4 p2 = __ldcs(pred4 + b + 16);

        float r = day_err_sq(t0, p0, thresh)
                + day_err_sq(t1, p1, thresh)
                + day_err_sq(t2, p2, thresh);

        // reduce within 8-lane group (xor of low 3 bits stays in-group)
        r += __shfl_xor_sync(0xffffffffu, r, 4);
        r += __shfl_xor_sync(0xffffffffu, r, 2);
        r += __shfl_xor_sync(0xffffffffu, r, 1);

        acc += (1.0f - sqrtf(r * inv_T)) * 100.0f;   // counted 8x per day
    }

    // tail: 0..3 days, groups g < nd active, same float4 path
    {
        const int nd = day_e - day;
        if (nd > 0) {
            float r = 0.0f;
            if (g < nd) {
                const long b = (long)(day + g) * F4_PER_DAY + k;
                float4 t0 = __ldcs(tru4  + b);
                float4 t1 = __ldcs(tru4  + b + 8);
                float4 t2 = __ldcs(tru4  + b + 16);
                float4 p0 = __ldcs(pred4 + b);
                float4 p1 = __ldcs(pred4 + b + 8);
                float4 p2 = __ldcs(pred4 + b + 16);
                r = day_err_sq(t0, p0, thresh)
                  + day_err_sq(t1, p1, thresh)
                  + day_err_sq(t2, p2, thresh);
            }
            r += __shfl_xor_sync(0xffffffffu, r, 4);
            r += __shfl_xor_sync(0xffffffffu, r, 2);
            r += __shfl_xor_sync(0xffffffffu, r, 1);
            if (g < nd)
                acc += (1.0f - sqrtf(r * inv_T)) * 100.0f;
        }
    }

    // warp sum, then block reduce into g_partials[blockIdx.x]
    #pragma unroll
    for (int o = 16; o > 0; o >>= 1)
        acc += __shfl_xor_sync(0xffffffffu, acc, o);

    __shared__ float warp_acc[WARPS_PER_BLOCK];
    if (lane == 0) warp_acc[threadIdx.x >> 5] = acc;
    __syncthreads();

    __shared__ bool is_last;
    if (threadIdx.x == 0) {
        float v = 0.0f;
        #pragma unroll
        for (int w = 0; w < WARPS_PER_BLOCK; w++) v += warp_acc[w];
        g_partials[blockIdx.x] = v;
        __threadfence();
        unsigned int prev = atomicAdd(&g_counter, 1u);
        is_last = (prev == (unsigned int)(gridDim.x - 1));
    }
    __syncthreads();

    // last block finalizes: fixed-order double reduction over NBLOCKS partials
    if (is_last) {
        double a = 0.0;
        for (int i = threadIdx.x; i < NBLOCKS; i += NTHREADS)
            a += (double)g_partials[i];

        __shared__ double dacc[WARPS_PER_BLOCK];
        #pragma unroll
        for (int o = 16; o > 0; o >>= 1)
            a += __shfl_xor_sync(0xffffffffu, a, o);
        if (lane == 0) dacc[threadIdx.x >> 5] = a;
        __syncthreads();
        if (threadIdx.x == 0) {
            double s = 0.0;
            #pragma unroll
            for (int w = 0; w < WARPS_PER_BLOCK; w++) s += dacc[w];
            out[0] = (float)(s / (8.0 * (double)num_days));
            g_counter = 0;           // reset for next graph replay
            __threadfence();
        }
    }
}

extern "C" void kernel_launch(void* const* d_in, const int* in_sizes, int n_in,
                              void* d_out, int out_size)
{
    const float* pred = (const float*)d_in[0];
    const float* tru  = (const float*)d_in[1];
    float* out = (float*)d_out;

    int num_days = in_sizes[0] / T_LEN;

    score_kernel<<<NBLOCKS, NTHREADS>>>(pred, tru, out, num_days);
}

// round 15
// speedup vs baseline: 1.0021x; 1.0021x over previous
#include <cuda_runtime.h>

// AccuracyMetricLoss: per-day (96-elem) RMS relative-error score, mean over days.
// score_d = (1 - sqrt(mean_j ((t-p)/max(t,thresh))^2)) * 100 ; out = mean_d score_d
//
// FINAL — converged, reproduced 4x at 31.20-31.26us (ncu 30.1-32.0us across
// NAT clock jitter; 4.9-5.2TB/s). Work floor: 153.6MB irreducible reads.
// Empirical platform ceiling: ~5.1TB/s, shown path-independent by the R4-R12
// matrix (LDG occ 37-93%, scalar/float4/register-pipelined, ldcs/default,
// cp.async.bulk TMA pipeline — all in 4.7-5.2TB/s). This kernel operates at
// that ceiling with launch overhead fused (last-block-finalize), deterministic
// accumulation, and graph-replayable state.
//
//  - 8-lanes-per-day float4 layout: 6 batched, fully-coalesced LDG.128/trip.
//  - __ldcs evict-first streaming (153.6MB >> 126MB L2; default policy -10%).
//  - __launch_bounds__(256,4), 592 blocks, contiguous per-warp day ranges.
//  - 3-shuffle in-group reduction; score counted 8x/day, divided at finalize.

#define T_LEN 96
#define F4_PER_DAY 24
#define NBLOCKS 592          // 4 * 148 SMs
#define NTHREADS 256         // 8 warps/block
#define WARPS_PER_BLOCK (NTHREADS / 32)
#define TOTAL_WARPS (NBLOCKS * WARPS_PER_BLOCK)

__device__ float g_partials[NBLOCKS];
__device__ unsigned int g_counter = 0;

__device__ __forceinline__ float day_err_sq(float4 t, float4 p, float thresh)
{
    float d0 = (t.x > thresh) ? t.x : thresh;
    float d1 = (t.y > thresh) ? t.y : thresh;
    float d2 = (t.z > thresh) ? t.z : thresh;
    float d3 = (t.w > thresh) ? t.w : thresh;
    float e0 = __fdividef(t.x - p.x, d0);
    float e1 = __fdividef(t.y - p.y, d1);
    float e2 = __fdividef(t.z - p.z, d2);
    float e3 = __fdividef(t.w - p.w, d3);
    return e0 * e0 + e1 * e1 + e2 * e2 + e3 * e3;
}

__global__ __launch_bounds__(NTHREADS, 4) void score_kernel(
    const float* __restrict__ pred,
    const float* __restrict__ tru,
    float* __restrict__ out,
    int num_days)
{
    const float cap    = 1602.1333333333334f;
    const float thresh = 0.2f * cap;
    const float inv_T  = 1.0f / 96.0f;

    const int lane = threadIdx.x & 31;
    const int g    = lane >> 3;          // day group within warp (0..3)
    const int k    = lane & 7;           // lane within group
    const int warp = (blockIdx.x * WARPS_PER_BLOCK) + (threadIdx.x >> 5);

    const float4* __restrict__ tru4  = (const float4*)tru;
    const float4* __restrict__ pred4 = (const float4*)pred;

    // contiguous per-warp day range: near-perfect balance (<=1 day skew)
    int day_s = (int)(((long)warp       * num_days) / TOTAL_WARPS);
    int day_e = (int)(((long)(warp + 1) * num_days) / TOTAL_WARPS);

    float acc = 0.0f;

    int day = day_s;
    for (; day + 4 <= day_e; day += 4) {
        // 6 fully-coalesced LDG.128 per warp, batched
        const long b = (long)(day + g) * F4_PER_DAY + k;
        float4 t0 = __ldcs(tru4  + b);
        float4 t1 = __ldcs(tru4  + b + 8);
        float4 t2 = __ldcs(tru4  + b + 16);
        float4 p0 = __ldcs(pred4 + b);
        float4 p1 = __ldcs(pred4 + b + 8);
        float4 p2 = __ldcs(pred4 + b + 16);

        float r = day_err_sq(t0, p0, thresh)
                + day_err_sq(t1, p1, thresh)
                + day_err_sq(t2, p2, thresh);

        // reduce within 8-lane group (xor of low 3 bits stays in-group)
        r += __shfl_xor_sync(0xffffffffu, r, 4);
        r += __shfl_xor_sync(0xffffffffu, r, 2);
        r += __shfl_xor_sync(0xffffffffu, r, 1);

        acc += (1.0f - sqrtf(r * inv_T)) * 100.0f;   // counted 8x per day
    }

    // tail: 0..3 days, groups g < nd active, same float4 path
    {
        const int nd = day_e - day;
        if (nd > 0) {
            float r = 0.0f;
            if (g < nd) {
                const long b = (long)(day + g) * F4_PER_DAY + k;
                float4 t0 = __ldcs(tru4  + b);
                float4 t1 = __ldcs(tru4  + b + 8);
                float4 t2 = __ldcs(tru4  + b + 16);
                float4 p0 = __ldcs(pred4 + b);
                float4 p1 = __ldcs(pred4 + b + 8);
                float4 p2 = __ldcs(pred4 + b + 16);
                r = day_err_sq(t0, p0, thresh)
                  + day_err_sq(t1, p1, thresh)
                  + day_err_sq(t2, p2, thresh);
            }
            r += __shfl_xor_sync(0xffffffffu, r, 4);
            r += __shfl_xor_sync(0xffffffffu, r, 2);
            r += __shfl_xor_sync(0xffffffffu, r, 1);
            if (g < nd)
                acc += (1.0f - sqrtf(r * inv_T)) * 100.0f;
        }
    }

    // warp sum, then block reduce into g_partials[blockIdx.x]
    #pragma unroll
    for (int o = 16; o > 0; o >>= 1)
        acc += __shfl_xor_sync(0xffffffffu, acc, o);

    __shared__ float warp_acc[WARPS_PER_BLOCK];
    if (lane == 0) warp_acc[threadIdx.x >> 5] = acc;
    __syncthreads();

    __shared__ bool is_last;
    if (threadIdx.x == 0) {
        float v = 0.0f;
        #pragma unroll
        for (int w = 0; w < WARPS_PER_BLOCK; w++) v += warp_acc[w];
        g_partials[blockIdx.x] = v;
        __threadfence();
        unsigned int prev = atomicAdd(&g_counter, 1u);
        is_last = (prev == (unsigned int)(gridDim.x - 1));
    }
    __syncthreads();

    // last block finalizes: fixed-order double reduction over NBLOCKS partials
    if (is_last) {
        double a = 0.0;
        for (int i = threadIdx.x; i < NBLOCKS; i += NTHREADS)
            a += (double)g_partials[i];

        __shared__ double dacc[WARPS_PER_BLOCK];
        #pragma unroll
        for (int o = 16; o > 0; o >>= 1)
            a += __shfl_xor_sync(0xffffffffu, a, o);
        if (lane == 0) dacc[threadIdx.x >> 5] = a;
        __syncthreads();
        if (threadIdx.x == 0) {
            double s = 0.0;
            #pragma unroll
            for (int w = 0; w < WARPS_PER_BLOCK; w++) s += dacc[w];
            out[0] = (float)(s / (8.0 * (double)num_days));
            g_counter = 0;           // reset for next graph replay
            __threadfence();
        }
    }
}

extern "C" void kernel_launch(void* const* d_in, const int* in_sizes, int n_in,
                              void* d_out, int out_size)
{
    const float* pred = (const float*)d_in[0];
    const float* tru  = (const float*)d_in[1];
    float* out = (float*)d_out;

    int num_days = in_sizes[0] / T_LEN;

    score_kernel<<<NBLOCKS, NTHREADS>>>(pred, tru, out, num_days);
}